// round 4
// baseline (speedup 1.0000x reference)
#include <cuda_runtime.h>
#include <cuda_bf16.h>
#include <cstdint>

#define N_NODES 100000
#define N_EDGES 6400000
#define TOKEN_DIM 16

// Scratch accumulator (no cudaMalloc allowed anywhere).
__device__ float g_local_field[N_NODES];

// ---------------------------------------------------------------------------
// Kernel 1: edge scatter.  bond = x[row]*x[col]; REDG add into local_field[row].
// edge_index is INT32 (jax x64 disabled -> the int64 request silently becomes
// int32), layout [2, E]: rows at [0,E), cols at [E,2E).
// 4 edges/thread with int4 128-bit index loads.
// ---------------------------------------------------------------------------
__global__ void edge_scatter_kernel(const float* __restrict__ x,
                                    const int* __restrict__ edge_index)
{
    int q = blockIdx.x * blockDim.x + threadIdx.x;   // quad index
    int e = q * 4;
    if (e >= N_EDGES) return;

    int4 r = *reinterpret_cast<const int4*>(edge_index + e);
    int4 c = *reinterpret_cast<const int4*>(edge_index + N_EDGES + e);

    float b0 = __ldg(&x[r.x]) * __ldg(&x[c.x]);
    float b1 = __ldg(&x[r.y]) * __ldg(&x[c.y]);
    float b2 = __ldg(&x[r.z]) * __ldg(&x[c.z]);
    float b3 = __ldg(&x[r.w]) * __ldg(&x[c.w]);

    atomicAdd(&g_local_field[r.x], b0);
    atomicAdd(&g_local_field[r.y], b1);
    atomicAdd(&g_local_field[r.z], b2);
    atomicAdd(&g_local_field[r.w], b3);
}

// ---------------------------------------------------------------------------
// Kernel 2: per-node 2-layer MLP (weights broadcast from shared).
// ---------------------------------------------------------------------------
__global__ void node_mlp_kernel(const float* __restrict__ x,
                                const float* __restrict__ w1,
                                const float* __restrict__ b1,
                                const float* __restrict__ w2,
                                const float* __restrict__ b2,
                                float* __restrict__ out)
{
    __shared__ float s_w1[TOKEN_DIM * 2];
    __shared__ float s_b1[TOKEN_DIM];
    __shared__ float s_w2[TOKEN_DIM * TOKEN_DIM];
    __shared__ float s_b2[TOKEN_DIM];

    int t = threadIdx.x;
    if (t < TOKEN_DIM * 2)         s_w1[t] = __ldg(&w1[t]);
    if (t < TOKEN_DIM)             s_b1[t] = __ldg(&b1[t]);
    if (t < TOKEN_DIM * TOKEN_DIM) s_w2[t] = __ldg(&w2[t]);
    if (t >= 256 && t < 256 + TOKEN_DIM) s_b2[t - 256] = __ldg(&b2[t - 256]);
    __syncthreads();

    int i = blockIdx.x * blockDim.x + t;
    if (i >= N_NODES) return;

    float s  = x[i];
    float lf = g_local_field[i];

    float h[TOKEN_DIM];
    #pragma unroll
    for (int j = 0; j < TOKEN_DIM; j++) {
        float v = fmaf(s, s_w1[2 * j], fmaf(lf, s_w1[2 * j + 1], s_b1[j]));
        h[j] = fmaxf(v, 0.0f);
    }

    float tok[TOKEN_DIM];
    #pragma unroll
    for (int k = 0; k < TOKEN_DIM; k++) {
        float acc = s_b2[k];
        #pragma unroll
        for (int j = 0; j < TOKEN_DIM; j++)
            acc = fmaf(h[j], s_w2[k * TOKEN_DIM + j], acc);
        tok[k] = fmaxf(acc, 0.0f);
    }

    float4* o4 = reinterpret_cast<float4*>(out + (size_t)i * TOKEN_DIM);
    #pragma unroll
    for (int qo = 0; qo < 4; qo++)
        o4[qo] = make_float4(tok[4 * qo + 0], tok[4 * qo + 1],
                             tok[4 * qo + 2], tok[4 * qo + 3]);
}

extern "C" void kernel_launch(void* const* d_in, const int* in_sizes, int n_in,
                              void* d_out, int out_size)
{
    // Identify inputs by element count (robust to metadata ordering):
    //   x          -> 100000
    //   edge_index -> 12800000 (2 * 6400000, int32)
    //   w1         -> 32   (16x2)
    //   w2         -> 256  (16x16)
    //   b1, b2     -> 16 each (b1 = first occurrence, b2 = second)
    const float* x  = nullptr;
    const int*   ei = nullptr;
    const float* w1 = nullptr;
    const float* b1 = nullptr;
    const float* w2 = nullptr;
    const float* b2 = nullptr;

    for (int i = 0; i < n_in; i++) {
        switch (in_sizes[i]) {
            case N_NODES:       x  = (const float*)d_in[i]; break;
            case 2 * N_EDGES:   ei = (const int*)d_in[i];   break;
            case TOKEN_DIM * 2: w1 = (const float*)d_in[i]; break;
            case TOKEN_DIM * TOKEN_DIM: w2 = (const float*)d_in[i]; break;
            case TOKEN_DIM:
                if (!b1) b1 = (const float*)d_in[i];
                else     b2 = (const float*)d_in[i];
                break;
            default: break;
        }
    }

    float* out = (float*)d_out;

    void* lf_ptr = nullptr;
    cudaGetSymbolAddress(&lf_ptr, g_local_field);
    cudaMemsetAsync(lf_ptr, 0, N_NODES * sizeof(float));

    {
        int quads = N_EDGES / 4;
        int threads = 256;
        int blocks = (quads + threads - 1) / threads;
        edge_scatter_kernel<<<blocks, threads>>>(x, ei);
    }
    {
        int threads = 512;
        int blocks = (N_NODES + threads - 1) / threads;
        node_mlp_kernel<<<blocks, threads>>>(x, w1, b1, w2, b2, out);
    }
}

// round 8
// speedup vs baseline: 1.1932x; 1.1932x over previous
#include <cuda_runtime.h>
#include <cuda_bf16.h>
#include <cstdint>

#define N_NODES 100000
#define N_EDGES 6400000
#define TOKEN_DIM 16

// Scratch accumulator: t[n] = sum of x[col[e]] over edges with row[e]==n.
// (local_field[n] = x[n] * t[n], multiply applied in the node kernel.)
__device__ float g_t[N_NODES];

// ---------------------------------------------------------------------------
// Kernel 1: edge scatter, restructured to 1 gather + 1 reduction per edge:
//     t[row[e]] += x[col[e]]
// edge_index is INT32, layout [2, E]: rows at [0,E), cols at [E,2E).
// 8 edges/thread with int4 128-bit index loads.
// ---------------------------------------------------------------------------
__global__ void edge_scatter_kernel(const float* __restrict__ x,
                                    const int* __restrict__ edge_index)
{
    int q = blockIdx.x * blockDim.x + threadIdx.x;   // octet index
    long e = (long)q * 8;
    if (e >= N_EDGES) return;

    int4 r0 = *reinterpret_cast<const int4*>(edge_index + e);
    int4 r1 = *reinterpret_cast<const int4*>(edge_index + e + 4);
    int4 c0 = *reinterpret_cast<const int4*>(edge_index + N_EDGES + e);
    int4 c1 = *reinterpret_cast<const int4*>(edge_index + N_EDGES + e + 4);

    float v0 = __ldg(&x[c0.x]);
    float v1 = __ldg(&x[c0.y]);
    float v2 = __ldg(&x[c0.z]);
    float v3 = __ldg(&x[c0.w]);
    float v4 = __ldg(&x[c1.x]);
    float v5 = __ldg(&x[c1.y]);
    float v6 = __ldg(&x[c1.z]);
    float v7 = __ldg(&x[c1.w]);

    atomicAdd(&g_t[r0.x], v0);
    atomicAdd(&g_t[r0.y], v1);
    atomicAdd(&g_t[r0.z], v2);
    atomicAdd(&g_t[r0.w], v3);
    atomicAdd(&g_t[r1.x], v4);
    atomicAdd(&g_t[r1.y], v5);
    atomicAdd(&g_t[r1.z], v6);
    atomicAdd(&g_t[r1.w], v7);
}

// ---------------------------------------------------------------------------
// Kernel 2: per-node 2-layer MLP (weights broadcast from shared).
// lf = x[i] * t[i]  (restructured edge sum).
// NOTE: blockDim must be >= 256 so all of s_w2 is loaded.
// ---------------------------------------------------------------------------
__global__ void node_mlp_kernel(const float* __restrict__ x,
                                const float* __restrict__ w1,
                                const float* __restrict__ b1,
                                const float* __restrict__ w2,
                                const float* __restrict__ b2,
                                float* __restrict__ out)
{
    __shared__ float s_w1[TOKEN_DIM * 2];
    __shared__ float s_b1[TOKEN_DIM];
    __shared__ float s_w2[TOKEN_DIM * TOKEN_DIM];
    __shared__ float s_b2[TOKEN_DIM];

    int t = threadIdx.x;
    if (t < TOKEN_DIM * 2)         s_w1[t] = __ldg(&w1[t]);
    if (t < TOKEN_DIM)             s_b1[t] = __ldg(&b1[t]);
    if (t < TOKEN_DIM * TOKEN_DIM) s_w2[t] = __ldg(&w2[t]);  // needs blockDim >= 256
    if (t >= 32 && t < 32 + TOKEN_DIM) s_b2[t - 32] = __ldg(&b2[t - 32]);
    __syncthreads();

    int i = blockIdx.x * blockDim.x + t;
    if (i >= N_NODES) return;

    float s  = x[i];
    float lf = s * g_t[i];

    float h[TOKEN_DIM];
    #pragma unroll
    for (int j = 0; j < TOKEN_DIM; j++) {
        float v = fmaf(s, s_w1[2 * j], fmaf(lf, s_w1[2 * j + 1], s_b1[j]));
        h[j] = fmaxf(v, 0.0f);
    }

    float tok[TOKEN_DIM];
    #pragma unroll
    for (int k = 0; k < TOKEN_DIM; k++) {
        float acc = s_b2[k];
        #pragma unroll
        for (int j = 0; j < TOKEN_DIM; j++)
            acc = fmaf(h[j], s_w2[k * TOKEN_DIM + j], acc);
        tok[k] = fmaxf(acc, 0.0f);
    }

    float4* o4 = reinterpret_cast<float4*>(out + (size_t)i * TOKEN_DIM);
    #pragma unroll
    for (int qo = 0; qo < 4; qo++)
        o4[qo] = make_float4(tok[4 * qo + 0], tok[4 * qo + 1],
                             tok[4 * qo + 2], tok[4 * qo + 3]);
}

extern "C" void kernel_launch(void* const* d_in, const int* in_sizes, int n_in,
                              void* d_out, int out_size)
{
    // Identify inputs by element count (robust to metadata ordering):
    const float* x  = nullptr;
    const int*   ei = nullptr;
    const float* w1 = nullptr;
    const float* b1 = nullptr;
    const float* w2 = nullptr;
    const float* b2 = nullptr;

    for (int i = 0; i < n_in; i++) {
        switch (in_sizes[i]) {
            case N_NODES:       x  = (const float*)d_in[i]; break;
            case 2 * N_EDGES:   ei = (const int*)d_in[i];   break;
            case TOKEN_DIM * 2: w1 = (const float*)d_in[i]; break;
            case TOKEN_DIM * TOKEN_DIM: w2 = (const float*)d_in[i]; break;
            case TOKEN_DIM:
                if (!b1) b1 = (const float*)d_in[i];
                else     b2 = (const float*)d_in[i];
                break;
            default: break;
        }
    }

    float* out = (float*)d_out;

    void* t_ptr = nullptr;
    cudaGetSymbolAddress(&t_ptr, g_t);
    cudaMemsetAsync(t_ptr, 0, N_NODES * sizeof(float));

    {
        int octs = N_EDGES / 8;           // 800K threads
        int threads = 256;
        int blocks = (octs + threads - 1) / threads;
        edge_scatter_kernel<<<blocks, threads>>>(x, ei);
    }
    {
        int threads = 256;                               // >= 256 for s_w2 load
        int blocks = (N_NODES + threads - 1) / threads;  // 391 blocks
        node_mlp_kernel<<<blocks, threads>>>(x, w1, b1, w2, b2, out);
    }
}

// round 9
// speedup vs baseline: 1.2252x; 1.0269x over previous
#include <cuda_runtime.h>
#include <cuda_bf16.h>
#include <cstdint>

#define N_NODES 100000
#define N_EDGES 6400000
#define TOKEN_DIM 16

// Scratch accumulator: t[n] = sum of x[col[e]] over edges with row[e]==n.
// (local_field[n] = x[n] * t[n], multiply applied in the node kernel.)
// Zero-initialized at module load; node_mlp_kernel restores it to zero after
// consuming it, so every kernel_launch (and every graph replay) starts from
// zeros with NO memset launch.
__device__ float g_t[N_NODES];

// ---------------------------------------------------------------------------
// Kernel 1: edge scatter, 1 gather + 1 REDG per edge:
//     t[row[e]] += x[col[e]]
// edge_index is INT32, layout [2, E]: rows at [0,E), cols at [E,2E).
// 8 edges/thread with int4 128-bit index loads.
// ---------------------------------------------------------------------------
__global__ void edge_scatter_kernel(const float* __restrict__ x,
                                    const int* __restrict__ edge_index)
{
    int q = blockIdx.x * blockDim.x + threadIdx.x;   // octet index
    long e = (long)q * 8;
    if (e >= N_EDGES) return;

    int4 r0 = *reinterpret_cast<const int4*>(edge_index + e);
    int4 r1 = *reinterpret_cast<const int4*>(edge_index + e + 4);
    int4 c0 = *reinterpret_cast<const int4*>(edge_index + N_EDGES + e);
    int4 c1 = *reinterpret_cast<const int4*>(edge_index + N_EDGES + e + 4);

    float v0 = __ldg(&x[c0.x]);
    float v1 = __ldg(&x[c0.y]);
    float v2 = __ldg(&x[c0.z]);
    float v3 = __ldg(&x[c0.w]);
    float v4 = __ldg(&x[c1.x]);
    float v5 = __ldg(&x[c1.y]);
    float v6 = __ldg(&x[c1.z]);
    float v7 = __ldg(&x[c1.w]);

    atomicAdd(&g_t[r0.x], v0);
    atomicAdd(&g_t[r0.y], v1);
    atomicAdd(&g_t[r0.z], v2);
    atomicAdd(&g_t[r0.w], v3);
    atomicAdd(&g_t[r1.x], v4);
    atomicAdd(&g_t[r1.y], v5);
    atomicAdd(&g_t[r1.z], v6);
    atomicAdd(&g_t[r1.w], v7);
}

// ---------------------------------------------------------------------------
// Kernel 2: per-node 2-layer MLP. 128-thread blocks (782 blocks -> good SM
// balance). w2 rows read as float4 (LDS.128) to cut MIO ops 4x.
// Self-cleans g_t for the next graph replay.
// ---------------------------------------------------------------------------
__global__ void __launch_bounds__(128) node_mlp_kernel(
                                const float* __restrict__ x,
                                const float* __restrict__ w1,
                                const float* __restrict__ b1,
                                const float* __restrict__ w2,
                                const float* __restrict__ b2,
                                float* __restrict__ out)
{
    __shared__ float4 s_w2v[TOKEN_DIM * 4];   // 16 rows x 4 float4 each
    __shared__ float  s_w1[TOKEN_DIM * 2];
    __shared__ float  s_b1[TOKEN_DIM];
    __shared__ float  s_b2[TOKEN_DIM];

    int t = threadIdx.x;                       // blockDim == 128
    if (t < 64)              s_w2v[t] = reinterpret_cast<const float4*>(w2)[t];
    else if (t < 96)         s_w1[t - 64] = __ldg(&w1[t - 64]);
    else if (t < 112)        s_b1[t - 96] = __ldg(&b1[t - 96]);
    else                     s_b2[t - 112] = __ldg(&b2[t - 112]);
    __syncthreads();

    int i = blockIdx.x * blockDim.x + t;
    if (i >= N_NODES) return;

    float s  = x[i];
    float lf = s * g_t[i];
    g_t[i] = 0.0f;                             // restore zero-invariant

    float h[TOKEN_DIM];
    #pragma unroll
    for (int j = 0; j < TOKEN_DIM; j++) {
        float v = fmaf(s, s_w1[2 * j], fmaf(lf, s_w1[2 * j + 1], s_b1[j]));
        h[j] = fmaxf(v, 0.0f);
    }

    float tok[TOKEN_DIM];
    #pragma unroll
    for (int k = 0; k < TOKEN_DIM; k++) {
        float acc = s_b2[k];
        #pragma unroll
        for (int q4 = 0; q4 < 4; q4++) {
            float4 w = s_w2v[k * 4 + q4];
            acc = fmaf(h[4 * q4 + 0], w.x, acc);
            acc = fmaf(h[4 * q4 + 1], w.y, acc);
            acc = fmaf(h[4 * q4 + 2], w.z, acc);
            acc = fmaf(h[4 * q4 + 3], w.w, acc);
        }
        tok[k] = fmaxf(acc, 0.0f);
    }

    float4* o4 = reinterpret_cast<float4*>(out + (size_t)i * TOKEN_DIM);
    #pragma unroll
    for (int qo = 0; qo < 4; qo++)
        o4[qo] = make_float4(tok[4 * qo + 0], tok[4 * qo + 1],
                             tok[4 * qo + 2], tok[4 * qo + 3]);
}

extern "C" void kernel_launch(void* const* d_in, const int* in_sizes, int n_in,
                              void* d_out, int out_size)
{
    // Identify inputs by element count (robust to metadata ordering):
    const float* x  = nullptr;
    const int*   ei = nullptr;
    const float* w1 = nullptr;
    const float* b1 = nullptr;
    const float* w2 = nullptr;
    const float* b2 = nullptr;

    for (int i = 0; i < n_in; i++) {
        switch (in_sizes[i]) {
            case N_NODES:       x  = (const float*)d_in[i]; break;
            case 2 * N_EDGES:   ei = (const int*)d_in[i];   break;
            case TOKEN_DIM * 2: w1 = (const float*)d_in[i]; break;
            case TOKEN_DIM * TOKEN_DIM: w2 = (const float*)d_in[i]; break;
            case TOKEN_DIM:
                if (!b1) b1 = (const float*)d_in[i];
                else     b2 = (const float*)d_in[i];
                break;
            default: break;
        }
    }

    float* out = (float*)d_out;

    {
        int octs = N_EDGES / 8;           // 800K threads
        int threads = 256;
        int blocks = (octs + threads - 1) / threads;
        edge_scatter_kernel<<<blocks, threads>>>(x, ei);
    }
    {
        int threads = 128;
        int blocks = (N_NODES + threads - 1) / threads;   // 782 blocks
        node_mlp_kernel<<<blocks, threads>>>(x, w1, b1, w2, b2, out);
    }
}